// round 4
// baseline (speedup 1.0000x reference)
#include <cuda_runtime.h>
#include <cstdint>

// Problem constants
#define N_TOK  131072      // 64 * 2048 tokens
#define DDIM   256         // embedding dim
#define KCODES 1024        // codebook size
#define COMMIT 0.25f

// Output layout (flattened concatenation of reference return tuple, fp32):
//   [0]                      loss
//   [1 .. 1+N*D)             quantized_st
//   [1+N*D]                  perplexity
//   [2+N*D .. 2+N*D+N*K)     encodings (one-hot)
#define Q_OFF  1
#define P_OFF  (1 + (size_t)N_TOK * DDIM)          // 33554433
#define E_OFF  (2 + (size_t)N_TOK * DDIM)          // 33554434

// ---------------- device scratch (small statics only) ----------------------
__device__ int   g_idx[N_TOK];                // 512 KB
__device__ float g_ehalf[KCODES];             // ||e_k||^2 / 2
__device__ float g_loss_acc;
__device__ int   g_hist[KCODES];

// ---------------- kernel 1: init (ehalf, zero hist/loss) -------------------
__global__ void init_kernel(const float* __restrict__ emb) {
    int k = blockIdx.x * 256 + threadIdx.x;
    if (k < KCODES) {
        const float4* row = (const float4*)(emb + (size_t)k * DDIM);
        float s = 0.f;
        #pragma unroll
        for (int i = 0; i < DDIM / 4; i++) {
            float4 v = row[i];
            s += v.x * v.x + v.y * v.y + v.z * v.z + v.w * v.w;
        }
        g_ehalf[k] = 0.5f * s;
        g_hist[k]  = 0;
    }
    if (k == 0) g_loss_acc = 0.f;
}

// ---------------- kernel 2: fused pre-linear + score + argmax --------------
// Per block: 128 tokens, 256 threads.
// Phase A: f_tile[128][256] = X_tile @ W^T + b, computed into smem (transposed
//          [k_f][row], padded), streaming W in 32-k chunks, two 128-col halves.
// Phase B: stream codebook in 128-code x 16-k chunks (double-buffered), 8x8
//          per thread, running argmax of (f.e - ||e||^2/2), cross-thread reduce.
//
// Smem layout (floats), phases alias:
//   f_s  [0 .. 33792)           : f tile, 256 x 132
//   buf  [33792 .. 38016)       : phase A x_s (32x132) | phase B e_buf0,e_buf1 (16x132 each)
//   aux  [38016 .. 43136)       : phase A w_s (32x132) | phase B ehalf(1024)+red_v(2048)+red_i(2048)
#define S_PAD 132
#define F_S_FLOATS (DDIM * S_PAD)              // 33792
#define BUF_FLOATS (32 * S_PAD)                // 4224
#define AUX_FLOATS (KCODES + 2048 + 2048)      // 5120
#define SC_SMEM_BYTES ((F_S_FLOATS + BUF_FLOATS + AUX_FLOATS) * 4)   // 172544

__device__ __forceinline__ void load_tile_T(float* dst, const float* __restrict__ src,
                                            int r0, int k0, int nk, int tid) {
    // dst[k][r] (S_PAD stride) <- src[(r0+r)*DDIM + k0 + k], r<128, k<nk (nk in {16,32})
    int nit = nk / 16;   // float4s: 128 * nk / 4 ; per-thread = nk/16 * 2? compute directly
    #pragma unroll
    for (int it = 0; it < 2 * (32 / 16); it++) {
        if (it >= 2 * nit) break;
        int t  = tid + it * 256;                 // up to 1024 float4s
        int r  = t / (nk / 4);
        int cc = (t % (nk / 4)) * 4;
        float4 v = *(const float4*)&src[(size_t)(r0 + r) * DDIM + k0 + cc];
        dst[(cc + 0) * S_PAD + r] = v.x;
        dst[(cc + 1) * S_PAD + r] = v.y;
        dst[(cc + 2) * S_PAD + r] = v.z;
        dst[(cc + 3) * S_PAD + r] = v.w;
    }
}

__global__ __launch_bounds__(256)
void fused_kernel(const float* __restrict__ X, const float* __restrict__ W,
                  const float* __restrict__ bias, const float* __restrict__ emb) {
    extern __shared__ float smem[];
    float* f_s = smem;
    float* buf = f_s + F_S_FLOATS;     // 4224 floats
    float* aux = buf + BUF_FLOATS;     // 5120 floats

    const int row0 = blockIdx.x * 128;
    const int tid  = threadIdx.x;
    const int ty   = tid / 16;   // 0..15 -> rows ty*8..+7
    const int tx   = tid % 16;   // 0..15 -> cols tx*8..+7 (within 128-col tile)

    // ===================== Phase A: f = X @ W^T + b =========================
    float* x_s = buf;    // [32][S_PAD]
    float* w_s = aux;    // [32][S_PAD]
    #pragma unroll
    for (int half = 0; half < 2; half++) {
        const int c0 = half * 128;       // f-column base
        float acc[8][8];
        #pragma unroll
        for (int i = 0; i < 8; i++)
            #pragma unroll
            for (int j = 0; j < 8; j++) acc[i][j] = 0.f;

        for (int k0 = 0; k0 < DDIM; k0 += 32) {
            __syncthreads();
            // x_s[k][r] <- X[row0+r][k0+k]   (128 rows x 32 k)
            #pragma unroll
            for (int it = 0; it < 4; it++) {
                int t  = tid + it * 256;         // 0..1023 float4s
                int r  = t >> 3;                 // 0..127
                int cc = (t & 7) * 4;            // 0..28
                float4 v = *(const float4*)&X[(size_t)(row0 + r) * DDIM + k0 + cc];
                x_s[(cc + 0) * S_PAD + r] = v.x;
                x_s[(cc + 1) * S_PAD + r] = v.y;
                x_s[(cc + 2) * S_PAD + r] = v.z;
                x_s[(cc + 3) * S_PAD + r] = v.w;
            }
            // w_s[k][c] <- W[c0+c][k0+k]     (128 cols x 32 k)
            #pragma unroll
            for (int it = 0; it < 4; it++) {
                int t  = tid + it * 256;
                int r  = t >> 3;
                int cc = (t & 7) * 4;
                float4 v = *(const float4*)&W[(size_t)(c0 + r) * DDIM + k0 + cc];
                w_s[(cc + 0) * S_PAD + r] = v.x;
                w_s[(cc + 1) * S_PAD + r] = v.y;
                w_s[(cc + 2) * S_PAD + r] = v.z;
                w_s[(cc + 3) * S_PAD + r] = v.w;
            }
            __syncthreads();
            #pragma unroll
            for (int k = 0; k < 32; k++) {
                float fr[8], wr[8];
                const float* xp = &x_s[k * S_PAD + ty * 8];
                *(float4*)&fr[0] = *(const float4*)(xp);
                *(float4*)&fr[4] = *(const float4*)(xp + 4);
                const float* wp = &w_s[k * S_PAD + tx * 8];
                *(float4*)&wr[0] = *(const float4*)(wp);
                *(float4*)&wr[4] = *(const float4*)(wp + 4);
                #pragma unroll
                for (int i = 0; i < 8; i++)
                    #pragma unroll
                    for (int j = 0; j < 8; j++) acc[i][j] += fr[i] * wr[j];
            }
        }
        // add bias, write transposed into f_s[col][row]
        #pragma unroll
        for (int j = 0; j < 8; j++) {
            int   col = c0 + tx * 8 + j;
            float bv  = bias[col];
            #pragma unroll
            for (int i = 0; i < 8; i++)
                f_s[(size_t)col * S_PAD + ty * 8 + i] = acc[i][j] + bv;
        }
    }
    __syncthreads();   // f_s complete; x_s/w_s regions free for phase B reuse

    // ===================== Phase B: score + argmax ==========================
    float* e_buf0  = buf;                  // [16][S_PAD]
    float* e_buf1  = buf + 16 * S_PAD;     // [16][S_PAD]
    float* ehalf_s = aux;                  // [1024]
    float* red_v   = aux + KCODES;         // [128][16]
    int*   red_i   = (int*)(red_v + 2048); // [128][16]

    #pragma unroll
    for (int w = 0; w < 4; w++) ehalf_s[tid + w * 256] = g_ehalf[tid + w * 256];

    float bestv[8];
    int   besti[8];
    #pragma unroll
    for (int i = 0; i < 8; i++) { bestv[i] = -1e30f; besti[i] = 0; }

    for (int c0 = 0; c0 < KCODES; c0 += 128) {
        float acc[8][8];
        #pragma unroll
        for (int i = 0; i < 8; i++)
            #pragma unroll
            for (int j = 0; j < 8; j++) acc[i][j] = 0.f;

        // prologue: fill buffer 0 with e[k=0..15]
        #pragma unroll
        for (int it = 0; it < 2; it++) {
            int t  = tid + it * 256;
            int r  = t >> 2;
            int cc = (t & 3) * 4;
            float4 v = *(const float4*)&emb[(size_t)(c0 + r) * DDIM + cc];
            e_buf0[(cc + 0) * S_PAD + r] = v.x;
            e_buf0[(cc + 1) * S_PAD + r] = v.y;
            e_buf0[(cc + 2) * S_PAD + r] = v.z;
            e_buf0[(cc + 3) * S_PAD + r] = v.w;
        }
        __syncthreads();

        #pragma unroll
        for (int kc = 0; kc < DDIM / 16; kc++) {
            float* e_cur = (kc & 1) ? e_buf1 : e_buf0;
            float* e_nxt = (kc & 1) ? e_buf0 : e_buf1;
            if (kc + 1 < DDIM / 16) {
                int k0n = (kc + 1) * 16;
                #pragma unroll
                for (int it = 0; it < 2; it++) {
                    int t  = tid + it * 256;
                    int r  = t >> 2;
                    int cc = (t & 3) * 4;
                    float4 v = *(const float4*)&emb[(size_t)(c0 + r) * DDIM + k0n + cc];
                    e_nxt[(cc + 0) * S_PAD + r] = v.x;
                    e_nxt[(cc + 1) * S_PAD + r] = v.y;
                    e_nxt[(cc + 2) * S_PAD + r] = v.z;
                    e_nxt[(cc + 3) * S_PAD + r] = v.w;
                }
            }
            const int k0 = kc * 16;
            #pragma unroll
            for (int k = 0; k < 16; k++) {
                float fr[8], er[8];
                const float* fp = &f_s[(k0 + k) * S_PAD + ty * 8];
                *(float4*)&fr[0] = *(const float4*)(fp);
                *(float4*)&fr[4] = *(const float4*)(fp + 4);
                const float* ep = &e_cur[k * S_PAD + tx * 8];
                *(float4*)&er[0] = *(const float4*)(ep);
                *(float4*)&er[4] = *(const float4*)(ep + 4);
                #pragma unroll
                for (int i = 0; i < 8; i++)
                    #pragma unroll
                    for (int j = 0; j < 8; j++) acc[i][j] += fr[i] * er[j];
            }
            __syncthreads();   // next buffer ready / cur buffer free
        }

        // running argmax (strict > keeps earliest index within this thread)
        #pragma unroll
        for (int j = 0; j < 8; j++) {
            int col = c0 + tx * 8 + j;
            float eh = ehalf_s[col];
            #pragma unroll
            for (int i = 0; i < 8; i++) {
                float sc = acc[i][j] - eh;
                if (sc > bestv[i]) { bestv[i] = sc; besti[i] = col; }
            }
        }
    }

    #pragma unroll
    for (int i = 0; i < 8; i++) {
        red_v[(ty * 8 + i) * 16 + tx] = bestv[i];
        red_i[(ty * 8 + i) * 16 + tx] = besti[i];
    }
    __syncthreads();
    if (tid < 128) {
        float bv = -1e30f;
        int   bi = 0x7fffffff;
        #pragma unroll
        for (int t = 0; t < 16; t++) {
            float v  = red_v[tid * 16 + t];
            int   ii = red_i[tid * 16 + t];
            if (v > bv || (v == bv && ii < bi)) { bv = v; bi = ii; }
        }
        g_idx[row0 + tid] = bi;
    }
}

// ---------------- kernel 3: quantize + straight-through + loss -------------
__global__ __launch_bounds__(256)
void quant_loss_kernel(const float* __restrict__ X, const float* __restrict__ emb,
                       float* __restrict__ out) {
    int i = blockIdx.x * 256 + threadIdx.x;      // 0 .. N*D-1 (fits int)
    int token = i >> 8;
    int dd    = i & 255;
    int id    = g_idx[token];
    float q    = emb[(size_t)id * DDIM + dd];
    float x    = X[i];
    float diff = q - x;                          // stop_grad(quantized - inputs)
    out[Q_OFF + (size_t)i] = x + diff;           // straight-through
    float s = diff * diff;

    #pragma unroll
    for (int o = 16; o > 0; o >>= 1) s += __shfl_down_sync(0xffffffffu, s, o);
    __shared__ float red[8];
    if ((threadIdx.x & 31) == 0) red[threadIdx.x >> 5] = s;
    __syncthreads();
    if (threadIdx.x == 0) {
        float t = 0.f;
        #pragma unroll
        for (int w = 0; w < 8; w++) t += red[w];
        atomicAdd(&g_loss_acc, t);
    }
}

// ---------------- kernel 4: one-hot encodings (zero + scatter) + hist ------
__global__ __launch_bounds__(256)
void enc_kernel(float* __restrict__ out) {
    int token = blockIdx.x;
    int id    = g_idx[token];
    float2* rowp = (float2*)(out + E_OFF) + (size_t)token * (KCODES / 2);
    int tid = threadIdx.x;
    #pragma unroll
    for (int w = 0; w < 2; w++) {
        int s = tid + w * 256;                   // float2 slot: cols [2s, 2s+1]
        float2 v = make_float2(0.f, 0.f);
        if ((id >> 1) == s) { if (id & 1) v.y = 1.f; else v.x = 1.f; }
        rowp[s] = v;
    }
    if (tid == 0) atomicAdd(&g_hist[id], 1);
}

// ---------------- kernel 5: finalize (loss, perplexity) --------------------
__global__ __launch_bounds__(1024)
void finalize_kernel(float* __restrict__ out) {
    int t = threadIdx.x;                         // 0..1023
    float p    = (float)g_hist[t] / (float)N_TOK;
    float term = -p * logf(p + 1e-10f);
    #pragma unroll
    for (int o = 16; o > 0; o >>= 1) term += __shfl_down_sync(0xffffffffu, term, o);
    __shared__ float red[32];
    if ((t & 31) == 0) red[t >> 5] = term;
    __syncthreads();
    if (t == 0) {
        float tot = 0.f;
        #pragma unroll
        for (int w = 0; w < 32; w++) tot += red[w];
        out[P_OFF] = expf(tot);
        out[0]     = COMMIT * g_loss_acc / (float)((size_t)N_TOK * DDIM);
    }
}

// ---------------- launch ----------------------------------------------------
extern "C" void kernel_launch(void* const* d_in, const int* in_sizes, int n_in,
                              void* d_out, int out_size) {
    const float* X    = (const float*)d_in[0];   // inputs [64,2048,256]
    const float* W    = (const float*)d_in[1];   // pre_w  [256,256]
    const float* bia  = (const float*)d_in[2];   // pre_b  [256]
    const float* emb  = (const float*)d_in[3];   // emb    [1024,256]
    float* out = (float*)d_out;

    // Opt-in smem above the 48KB default (idempotent; non-stream API).
    (void)cudaFuncSetAttribute(fused_kernel,
                               cudaFuncAttributeMaxDynamicSharedMemorySize,
                               SC_SMEM_BYTES);

    init_kernel<<<KCODES / 256, 256>>>(emb);
    fused_kernel<<<N_TOK / 128, 256, SC_SMEM_BYTES>>>(X, W, bia, emb);
    quant_loss_kernel<<<(N_TOK * DDIM) / 256, 256>>>(X, emb, out);
    enc_kernel<<<N_TOK, 256>>>(out);
    finalize_kernel<<<1, 1024>>>(out);
}

// round 6
// speedup vs baseline: 1.0013x; 1.0013x over previous
#include <cuda_runtime.h>
#include <cstdint>

// Problem constants
#define N_TOK  131072      // 64 * 2048 tokens
#define DDIM   256         // embedding dim
#define KCODES 1024        // codebook size
#define COMMIT 0.25f

// Output layout (flattened concatenation of reference return tuple, fp32):
//   [0]                      loss
//   [1 .. 1+N*D)             quantized_st
//   [1+N*D]                  perplexity
//   [2+N*D .. 2+N*D+N*K)     encodings (one-hot)
#define Q_OFF  1
#define P_OFF  (1 + (size_t)N_TOK * DDIM)          // 33554433
#define E_OFF  (2 + (size_t)N_TOK * DDIM)          // 33554434

// ---------------- device scratch (small statics only) ----------------------
__device__ int   g_idx[N_TOK];                // 512 KB
__device__ float g_ehalf[KCODES];             // ||e_k||^2 / 2
__device__ float g_loss_acc;
__device__ int   g_hist[KCODES];

// ---------------- kernel 1: init (ehalf, zero hist/loss) -------------------
__global__ void init_kernel(const float* __restrict__ emb) {
    int k = blockIdx.x * 256 + threadIdx.x;
    if (k < KCODES) {
        const float4* row = (const float4*)(emb + (size_t)k * DDIM);
        float s = 0.f;
        #pragma unroll
        for (int i = 0; i < DDIM / 4; i++) {
            float4 v = row[i];
            s += v.x * v.x + v.y * v.y + v.z * v.z + v.w * v.w;
        }
        g_ehalf[k] = 0.5f * s;
        g_hist[k]  = 0;
    }
    if (k == 0) g_loss_acc = 0.f;
}

// ---------------- kernel 2: fused pre-linear + score + argmax --------------
// Per block: 128 tokens, 256 threads.
// Phase A: f_tile[128][256] = X_tile @ W^T + b, computed into smem (transposed
//          [k_f][row], padded), streaming W in 32-k chunks, two 128-col halves.
// Phase B: stream codebook in 128-code x 16-k chunks (double-buffered), 8x8
//          per thread, running argmax of (f.e - ||e||^2/2), cross-thread reduce.
//
// Smem layout (floats), phases alias:
//   f_s  [0 .. 33792)           : f tile, 256 x 132
//   buf  [33792 .. 38016)       : phase A x_s (32x132) | phase B e_buf0,e_buf1 (16x132 each)
//   aux  [38016 .. 43136)       : phase A w_s (32x132) | phase B ehalf(1024)+red_v(2048)+red_i(2048)
#define S_PAD 132
#define F_S_FLOATS (DDIM * S_PAD)              // 33792
#define BUF_FLOATS (32 * S_PAD)                // 4224
#define AUX_FLOATS (KCODES + 2048 + 2048)      // 5120
#define SC_SMEM_BYTES ((F_S_FLOATS + BUF_FLOATS + AUX_FLOATS) * 4)   // 172544

__device__ __forceinline__ void load_tile_T(float* dst, const float* __restrict__ src,
                                            int r0, int k0, int nk, int tid) {
    // dst[k][r] (S_PAD stride) <- src[(r0+r)*DDIM + k0 + k], r<128, k<nk (nk in {16,32})
    int nit = nk / 16;   // float4s: 128 * nk / 4 ; per-thread = nk/16 * 2? compute directly
    #pragma unroll
    for (int it = 0; it < 2 * (32 / 16); it++) {
        if (it >= 2 * nit) break;
        int t  = tid + it * 256;                 // up to 1024 float4s
        int r  = t / (nk / 4);
        int cc = (t % (nk / 4)) * 4;
        float4 v = *(const float4*)&src[(size_t)(r0 + r) * DDIM + k0 + cc];
        dst[(cc + 0) * S_PAD + r] = v.x;
        dst[(cc + 1) * S_PAD + r] = v.y;
        dst[(cc + 2) * S_PAD + r] = v.z;
        dst[(cc + 3) * S_PAD + r] = v.w;
    }
}

__global__ __launch_bounds__(256)
void fused_kernel(const float* __restrict__ X, const float* __restrict__ W,
                  const float* __restrict__ bias, const float* __restrict__ emb) {
    extern __shared__ float smem[];
    float* f_s = smem;
    float* buf = f_s + F_S_FLOATS;     // 4224 floats
    float* aux = buf + BUF_FLOATS;     // 5120 floats

    const int row0 = blockIdx.x * 128;
    const int tid  = threadIdx.x;
    const int ty   = tid / 16;   // 0..15 -> rows ty*8..+7
    const int tx   = tid % 16;   // 0..15 -> cols tx*8..+7 (within 128-col tile)

    // ===================== Phase A: f = X @ W^T + b =========================
    float* x_s = buf;    // [32][S_PAD]
    float* w_s = aux;    // [32][S_PAD]
    #pragma unroll
    for (int half = 0; half < 2; half++) {
        const int c0 = half * 128;       // f-column base
        float acc[8][8];
        #pragma unroll
        for (int i = 0; i < 8; i++)
            #pragma unroll
            for (int j = 0; j < 8; j++) acc[i][j] = 0.f;

        for (int k0 = 0; k0 < DDIM; k0 += 32) {
            __syncthreads();
            // x_s[k][r] <- X[row0+r][k0+k]   (128 rows x 32 k)
            #pragma unroll
            for (int it = 0; it < 4; it++) {
                int t  = tid + it * 256;         // 0..1023 float4s
                int r  = t >> 3;                 // 0..127
                int cc = (t & 7) * 4;            // 0..28
                float4 v = *(const float4*)&X[(size_t)(row0 + r) * DDIM + k0 + cc];
                x_s[(cc + 0) * S_PAD + r] = v.x;
                x_s[(cc + 1) * S_PAD + r] = v.y;
                x_s[(cc + 2) * S_PAD + r] = v.z;
                x_s[(cc + 3) * S_PAD + r] = v.w;
            }
            // w_s[k][c] <- W[c0+c][k0+k]     (128 cols x 32 k)
            #pragma unroll
            for (int it = 0; it < 4; it++) {
                int t  = tid + it * 256;
                int r  = t >> 3;
                int cc = (t & 7) * 4;
                float4 v = *(const float4*)&W[(size_t)(c0 + r) * DDIM + k0 + cc];
                w_s[(cc + 0) * S_PAD + r] = v.x;
                w_s[(cc + 1) * S_PAD + r] = v.y;
                w_s[(cc + 2) * S_PAD + r] = v.z;
                w_s[(cc + 3) * S_PAD + r] = v.w;
            }
            __syncthreads();
            #pragma unroll
            for (int k = 0; k < 32; k++) {
                float fr[8], wr[8];
                const float* xp = &x_s[k * S_PAD + ty * 8];
                *(float4*)&fr[0] = *(const float4*)(xp);
                *(float4*)&fr[4] = *(const float4*)(xp + 4);
                const float* wp = &w_s[k * S_PAD + tx * 8];
                *(float4*)&wr[0] = *(const float4*)(wp);
                *(float4*)&wr[4] = *(const float4*)(wp + 4);
                #pragma unroll
                for (int i = 0; i < 8; i++)
                    #pragma unroll
                    for (int j = 0; j < 8; j++) acc[i][j] += fr[i] * wr[j];
            }
        }
        // add bias, write transposed into f_s[col][row]
        #pragma unroll
        for (int j = 0; j < 8; j++) {
            int   col = c0 + tx * 8 + j;
            float bv  = bias[col];
            #pragma unroll
            for (int i = 0; i < 8; i++)
                f_s[(size_t)col * S_PAD + ty * 8 + i] = acc[i][j] + bv;
        }
    }
    __syncthreads();   // f_s complete; x_s/w_s regions free for phase B reuse

    // ===================== Phase B: score + argmax ==========================
    float* e_buf0  = buf;                  // [16][S_PAD]
    float* e_buf1  = buf + 16 * S_PAD;     // [16][S_PAD]
    float* ehalf_s = aux;                  // [1024]
    float* red_v   = aux + KCODES;         // [128][16]
    int*   red_i   = (int*)(red_v + 2048); // [128][16]

    #pragma unroll
    for (int w = 0; w < 4; w++) ehalf_s[tid + w * 256] = g_ehalf[tid + w * 256];

    float bestv[8];
    int   besti[8];
    #pragma unroll
    for (int i = 0; i < 8; i++) { bestv[i] = -1e30f; besti[i] = 0; }

    for (int c0 = 0; c0 < KCODES; c0 += 128) {
        float acc[8][8];
        #pragma unroll
        for (int i = 0; i < 8; i++)
            #pragma unroll
            for (int j = 0; j < 8; j++) acc[i][j] = 0.f;

        // prologue: fill buffer 0 with e[k=0..15]
        #pragma unroll
        for (int it = 0; it < 2; it++) {
            int t  = tid + it * 256;
            int r  = t >> 2;
            int cc = (t & 3) * 4;
            float4 v = *(const float4*)&emb[(size_t)(c0 + r) * DDIM + cc];
            e_buf0[(cc + 0) * S_PAD + r] = v.x;
            e_buf0[(cc + 1) * S_PAD + r] = v.y;
            e_buf0[(cc + 2) * S_PAD + r] = v.z;
            e_buf0[(cc + 3) * S_PAD + r] = v.w;
        }
        __syncthreads();

        #pragma unroll
        for (int kc = 0; kc < DDIM / 16; kc++) {
            float* e_cur = (kc & 1) ? e_buf1 : e_buf0;
            float* e_nxt = (kc & 1) ? e_buf0 : e_buf1;
            if (kc + 1 < DDIM / 16) {
                int k0n = (kc + 1) * 16;
                #pragma unroll
                for (int it = 0; it < 2; it++) {
                    int t  = tid + it * 256;
                    int r  = t >> 2;
                    int cc = (t & 3) * 4;
                    float4 v = *(const float4*)&emb[(size_t)(c0 + r) * DDIM + k0n + cc];
                    e_nxt[(cc + 0) * S_PAD + r] = v.x;
                    e_nxt[(cc + 1) * S_PAD + r] = v.y;
                    e_nxt[(cc + 2) * S_PAD + r] = v.z;
                    e_nxt[(cc + 3) * S_PAD + r] = v.w;
                }
            }
            const int k0 = kc * 16;
            #pragma unroll
            for (int k = 0; k < 16; k++) {
                float fr[8], er[8];
                const float* fp = &f_s[(k0 + k) * S_PAD + ty * 8];
                *(float4*)&fr[0] = *(const float4*)(fp);
                *(float4*)&fr[4] = *(const float4*)(fp + 4);
                const float* ep = &e_cur[k * S_PAD + tx * 8];
                *(float4*)&er[0] = *(const float4*)(ep);
                *(float4*)&er[4] = *(const float4*)(ep + 4);
                #pragma unroll
                for (int i = 0; i < 8; i++)
                    #pragma unroll
                    for (int j = 0; j < 8; j++) acc[i][j] += fr[i] * er[j];
            }
            __syncthreads();   // next buffer ready / cur buffer free
        }

        // running argmax (strict > keeps earliest index within this thread)
        #pragma unroll
        for (int j = 0; j < 8; j++) {
            int col = c0 + tx * 8 + j;
            float eh = ehalf_s[col];
            #pragma unroll
            for (int i = 0; i < 8; i++) {
                float sc = acc[i][j] - eh;
                if (sc > bestv[i]) { bestv[i] = sc; besti[i] = col; }
            }
        }
    }

    #pragma unroll
    for (int i = 0; i < 8; i++) {
        red_v[(ty * 8 + i) * 16 + tx] = bestv[i];
        red_i[(ty * 8 + i) * 16 + tx] = besti[i];
    }
    __syncthreads();
    if (tid < 128) {
        float bv = -1e30f;
        int   bi = 0x7fffffff;
        #pragma unroll
        for (int t = 0; t < 16; t++) {
            float v  = red_v[tid * 16 + t];
            int   ii = red_i[tid * 16 + t];
            if (v > bv || (v == bv && ii < bi)) { bv = v; bi = ii; }
        }
        g_idx[row0 + tid] = bi;
    }
}

// ---------------- kernel 3: quantize + straight-through + loss -------------
__global__ __launch_bounds__(256)
void quant_loss_kernel(const float* __restrict__ X, const float* __restrict__ emb,
                       float* __restrict__ out) {
    int i = blockIdx.x * 256 + threadIdx.x;      // 0 .. N*D-1 (fits int)
    int token = i >> 8;
    int dd    = i & 255;
    int id    = g_idx[token];
    float q    = emb[(size_t)id * DDIM + dd];
    float x    = X[i];
    float diff = q - x;                          // stop_grad(quantized - inputs)
    out[Q_OFF + (size_t)i] = x + diff;           // straight-through
    float s = diff * diff;

    #pragma unroll
    for (int o = 16; o > 0; o >>= 1) s += __shfl_down_sync(0xffffffffu, s, o);
    __shared__ float red[8];
    if ((threadIdx.x & 31) == 0) red[threadIdx.x >> 5] = s;
    __syncthreads();
    if (threadIdx.x == 0) {
        float t = 0.f;
        #pragma unroll
        for (int w = 0; w < 8; w++) t += red[w];
        atomicAdd(&g_loss_acc, t);
    }
}

// ---------------- kernel 4: one-hot encodings (zero + scatter) + hist ------
__global__ __launch_bounds__(256)
void enc_kernel(float* __restrict__ out) {
    int token = blockIdx.x;
    int id    = g_idx[token];
    float2* rowp = (float2*)(out + E_OFF) + (size_t)token * (KCODES / 2);
    int tid = threadIdx.x;
    #pragma unroll
    for (int w = 0; w < 2; w++) {
        int s = tid + w * 256;                   // float2 slot: cols [2s, 2s+1]
        float2 v = make_float2(0.f, 0.f);
        if ((id >> 1) == s) { if (id & 1) v.y = 1.f; else v.x = 1.f; }
        rowp[s] = v;
    }
    if (tid == 0) atomicAdd(&g_hist[id], 1);
}

// ---------------- kernel 5: finalize (loss, perplexity) --------------------
__global__ __launch_bounds__(1024)
void finalize_kernel(float* __restrict__ out) {
    int t = threadIdx.x;                         // 0..1023
    float p    = (float)g_hist[t] / (float)N_TOK;
    float term = -p * logf(p + 1e-10f);
    #pragma unroll
    for (int o = 16; o > 0; o >>= 1) term += __shfl_down_sync(0xffffffffu, term, o);
    __shared__ float red[32];
    if ((t & 31) == 0) red[t >> 5] = term;
    __syncthreads();
    if (t == 0) {
        float tot = 0.f;
        #pragma unroll
        for (int w = 0; w < 32; w++) tot += red[w];
        out[P_OFF] = expf(tot);
        out[0]     = COMMIT * g_loss_acc / (float)((size_t)N_TOK * DDIM);
    }
}

// ---------------- launch ----------------------------------------------------
extern "C" void kernel_launch(void* const* d_in, const int* in_sizes, int n_in,
                              void* d_out, int out_size) {
    const float* X    = (const float*)d_in[0];   // inputs [64,2048,256]
    const float* W    = (const float*)d_in[1];   // pre_w  [256,256]
    const float* bia  = (const float*)d_in[2];   // pre_b  [256]
    const float* emb  = (const float*)d_in[3];   // emb    [1024,256]
    float* out = (float*)d_out;

    // Opt-in smem above the 48KB default (idempotent; non-stream API).
    (void)cudaFuncSetAttribute(fused_kernel,
                               cudaFuncAttributeMaxDynamicSharedMemorySize,
                               SC_SMEM_BYTES);

    init_kernel<<<KCODES / 256, 256>>>(emb);
    fused_kernel<<<N_TOK / 128, 256, SC_SMEM_BYTES>>>(X, W, bia, emb);
    quant_loss_kernel<<<(N_TOK * DDIM) / 256, 256>>>(X, emb, out);
    enc_kernel<<<N_TOK, 256>>>(out);
    finalize_kernel<<<1, 1024>>>(out);
}